// round 14
// baseline (speedup 1.0000x reference)
#include <cuda_runtime.h>
#include <math.h>

// ---------------------------------------------------------------------------
// AttentiveKnrmLayer  (B=64, NB=8, Q=32, T=256, D=256, N_BINS=11)
//
//  0 word_atten   [B,NB,Q]   f32      6 mask_can     [B,T]    f32
//  1 hq           [B,NB,Q,D] f32      7 mask_session [B,NB]   f32
//  2 can          [B,T,D]    f32      8 W_dense      [11,1]   f32
//  3 rep          [B,NB,D]   f32      9 b_dense      [1]      f32
//  4 rep_cur      [B,D]      f32     10 W_att        [D,D]    f32
//  5 mask_hq      [B,NB,Q]   f32     11 b_att        [D]      f32
//  output: [B] f32
//
// R13: packed-f32x2 GEMM (fma.rn.f32x2 -> FFMA2), inverse-norm-only kernel 1
// (no 21MB normalized copy), normalization folded into epilogue.
// ---------------------------------------------------------------------------

#define B_    64
#define NB_   8
#define Q_    32
#define T_    256
#define D_    256
#define NBIN  11

typedef unsigned long long ull_t;

// scratch (no cudaMalloc allowed)
__device__ float g_inv_hq[B_ * NB_ * Q_];   // 1/max(||hq row||, eps)
__device__ float g_inv_can[B_ * T_];        // 1/max(||can row||, eps)
__device__ float g_score[B_ * NB_];         // tanh(pooled @ W_dense + b)

// kern = exp(-(m-mu)^2/(2 s^2)) = exp2((m-mu)^2 * C2), C2 = -log2(e)/(2 s^2)
__constant__ float c_mu[NBIN] = {1.0f, 0.9f, 0.7f, 0.5f, 0.3f, 0.1f,
                                 -0.1f, -0.3f, -0.5f, -0.7f, -0.9f};
__constant__ float c_c2[NBIN] = {
    -721347.52f,
    -72.13475204f, -72.13475204f, -72.13475204f, -72.13475204f, -72.13475204f,
    -72.13475204f, -72.13475204f, -72.13475204f, -72.13475204f, -72.13475204f};

// packed dual-fp32 FMA: d = a*b + d  (elementwise on two fp32 lanes)
#define FMA2(d, a, b) \
    asm("fma.rn.f32x2 %0, %1, %2, %0;" : "+l"(d) : "l"(a), "l"(b))

// ---------------------------------------------------------------------------
// Kernel 1: inverse L2 norms only. One warp per 256-float row, float4 loads.
// rows [0,16384) -> hq, [16384,32768) -> can.
// ---------------------------------------------------------------------------
__global__ __launch_bounds__(256) void norms_kernel(
    const float* __restrict__ hq, const float* __restrict__ can)
{
    const int warp = threadIdx.x >> 5;
    const int lane = threadIdx.x & 31;
    const int row  = blockIdx.x * 8 + warp;

    const float* src;
    float* dst;
    if (row < B_ * NB_ * Q_) {
        src = hq + (size_t)row * D_;
        dst = g_inv_hq + row;
    } else {
        src = can + (size_t)(row - B_ * NB_ * Q_) * D_;
        dst = g_inv_can + (row - B_ * NB_ * Q_);
    }

    float4 v0 = *(const float4*)&src[lane * 4];
    float4 v1 = *(const float4*)&src[128 + lane * 4];
    float ss = v0.x * v0.x + v0.y * v0.y + v0.z * v0.z + v0.w * v0.w
             + v1.x * v1.x + v1.y * v1.y + v1.z * v1.z + v1.w * v1.w;
#pragma unroll
    for (int off = 16; off > 0; off >>= 1)
        ss += __shfl_xor_sync(0xffffffffu, ss, off);

    if (lane == 0)
        *dst = 1.0f / fmaxf(sqrtf(ss), 1e-10f);
}

// ---------------------------------------------------------------------------
// Kernel 2: per (b,n): fp32x2 GEMM (32x256 @ 256x256^T) fused with Gaussian
// soft-binning, log-pool over T, weighted sum over Q, dense + tanh.
//
// Grid (NB, B), block = 128 threads = 4 warps.
// Warp w owns q in [8w, 8w+8). Lane tt owns t in {j*32+tt : j<8}, held as
// 4 packed pairs p: (t=64p+tt, t=64p+32+tt).
//
// SMEM per K-chunk of 32:
//   cz : can chunk, pair-interleaved: cz[(p*32+tt)*68 + 2k+h] = can[64p+32h+tt][k]
//        -> LDS.128 yields two packed f32x2 B operands (k, k+1)
//   hq2: hq chunk duplicated:        hq2[q*68 + 2k+{0,1}] = hq[q][k]
//        -> broadcast LDS.128 yields two packed (a,a) operands
// Row stride 68 floats: 16B-aligned rows, conflict-free LDS.128 phases.
// ---------------------------------------------------------------------------
__global__ __launch_bounds__(128, 4) void knrm_kernel(
    const float* __restrict__ hq_g,
    const float* __restrict__ can_g,
    const float* __restrict__ word_atten,
    const float* __restrict__ mask_hq,
    const float* __restrict__ mask_can,
    const float* __restrict__ mask_session,
    const float* __restrict__ W_dense,
    const float* __restrict__ b_dense)
{
    const int n  = blockIdx.x;
    const int b  = blockIdx.y;
    const int bn = b * NB_ + n;

    const float* hqp = hq_g + (size_t)bn * Q_ * D_;
    const float* cnp = can_g + (size_t)b * T_ * D_;

    __shared__ __align__(16) float cz[128 * 68];   // 34816 B
    __shared__ __align__(16) float hq2[32 * 68];   //  8704 B
    __shared__ float lp_s[Q_][12];
    __shared__ float pooled_s[NBIN];

    const int tid = threadIdx.x;
    const int tt  = tid & 31;
    const int wid = tid >> 5;
    const int q0  = wid * 8;

    ull_t acc[8][4];
#pragma unroll
    for (int i = 0; i < 8; i++)
#pragma unroll
        for (int p = 0; p < 4; p++) acc[i][p] = 0ull;

    const int c  = tid & 7;    // float4 column in chunk (cs staging)
    const int r0 = tid >> 3;   // 0..15 (cs staging row slot)
    const int qs = tid >> 2;   // 0..31 (hq staging row)
    const int cc = tid & 3;    // hq staging col slot

    // ---- GEMM: K chunked by 32 --------------------------------------------
    for (int k0 = 0; k0 < D_; k0 += 32) {
        __syncthreads();   // previous chunk fully consumed

        // stage can chunk: 256 rows x 32 floats, pair-interleaved
#pragma unroll
        for (int pp = 0; pp < 16; pp++) {
            int t = r0 + 16 * pp;
            float4 v = *(const float4*)&cnp[(size_t)t * D_ + k0 + c * 4];
            int pr = ((t >> 6) << 5) + (t & 31);
            int h  = (t >> 5) & 1;
            float* d = &cz[pr * 68 + h];
            d[8 * c + 0] = v.x;
            d[8 * c + 2] = v.y;
            d[8 * c + 4] = v.z;
            d[8 * c + 6] = v.w;
        }
        // stage hq chunk: 32 rows x 32 floats, duplicated
#pragma unroll
        for (int u = 0; u < 2; u++) {
            float4 v = *(const float4*)&hqp[(size_t)qs * D_ + k0 + cc * 8 + u * 4];
            float* d = &hq2[qs * 68 + 2 * (8 * cc + 4 * u)];
            *(float2*)&d[0] = make_float2(v.x, v.x);
            *(float2*)&d[2] = make_float2(v.y, v.y);
            *(float2*)&d[4] = make_float2(v.z, v.z);
            *(float2*)&d[6] = make_float2(v.w, v.w);
        }
        __syncthreads();

#pragma unroll
        for (int kk = 0; kk < 32; kk += 4) {
            ulonglong2 b0[4], b1[4];
#pragma unroll
            for (int p = 0; p < 4; p++) {
                const float* base = &cz[(p * 32 + tt) * 68 + 2 * kk];
                b0[p] = *(const ulonglong2*)(base);       // k=kk, kk+1
                b1[p] = *(const ulonglong2*)(base + 4);   // k=kk+2, kk+3
            }
#pragma unroll
            for (int i = 0; i < 8; i++) {
                const float* ab = &hq2[(q0 + i) * 68 + 2 * kk];
                ulonglong2 a01 = *(const ulonglong2*)(ab);
                ulonglong2 a23 = *(const ulonglong2*)(ab + 4);
#pragma unroll
                for (int p = 0; p < 4; p++) {
                    FMA2(acc[i][p], a01.x, b0[p].x);
                    FMA2(acc[i][p], a01.y, b0[p].y);
                    FMA2(acc[i][p], a23.x, b1[p].x);
                    FMA2(acc[i][p], a23.y, b1[p].y);
                }
            }
        }
    }

    // ---- epilogue: normalize, Gaussian bins, pool over T -------------------
    float mc[8], it[8];
#pragma unroll
    for (int j = 0; j < 8; j++) {
        int t = j * 32 + tt;
        mc[j] = mask_can[b * T_ + t];
        it[j] = g_inv_can[b * T_ + t];
    }

#pragma unroll
    for (int i = 0; i < 8; i++) {
        const int q = q0 + i;
        const float invq = g_inv_hq[bn * Q_ + q];

        float bins[NBIN];
#pragma unroll
        for (int bb = 0; bb < NBIN; bb++) bins[bb] = 0.f;

#pragma unroll
        for (int p = 0; p < 4; p++) {
            ull_t v = acc[i][p];
            float mlo = __uint_as_float((unsigned)v)         * (invq * it[2 * p]);
            float mhi = __uint_as_float((unsigned)(v >> 32)) * (invq * it[2 * p + 1]);
            float wlo = mc[2 * p], whi = mc[2 * p + 1];
#pragma unroll
            for (int bb = 0; bb < NBIN; bb++) {
                float dl = mlo - c_mu[bb];
                float dh = mhi - c_mu[bb];
                bins[bb] += wlo * exp2f(dl * dl * c_c2[bb])
                          + whi * exp2f(dh * dh * c_c2[bb]);
            }
        }
#pragma unroll
        for (int bb = 0; bb < NBIN; bb++) {
            float s = bins[bb];
#pragma unroll
            for (int off = 16; off > 0; off >>= 1)
                s += __shfl_xor_sync(0xffffffffu, s, off);
            bins[bb] = s;
        }
        if (tt == 0) {
            float w = mask_hq[bn * Q_ + q] * word_atten[bn * Q_ + q];
#pragma unroll
            for (int bb = 0; bb < NBIN; bb++)
                lp_s[q][bb] = logf(fmaxf(bins[bb], 1e-10f)) * 0.01f * w;
        }
    }
    __syncthreads();

    // ---- sum over Q (fixed order), mask_session, dense + tanh --------------
    if (tid < NBIN) {
        float s = 0.f;
#pragma unroll
        for (int q = 0; q < Q_; q++) s += lp_s[q][tid];
        pooled_s[tid] = s * mask_session[bn];
    }
    __syncthreads();

    if (tid == 0) {
        float z = b_dense[0];
#pragma unroll
        for (int bb = 0; bb < NBIN; bb++) z += pooled_s[bb] * W_dense[bb];
        g_score[bn] = tanhf(z);
    }
}

// ---------------------------------------------------------------------------
// Kernel 3: session attention + final combine. One block per batch b.
// ---------------------------------------------------------------------------
__global__ __launch_bounds__(256) void attend_kernel(
    const float* __restrict__ rep,
    const float* __restrict__ rep_cur,
    const float* __restrict__ mask_session,
    const float* __restrict__ W_att,
    const float* __restrict__ b_att,
    float* __restrict__ out)
{
    const int b = blockIdx.x;
    const int tid = threadIdx.x;

    __shared__ float rc[D_];
    __shared__ float qv[D_];
    __shared__ float sc[NB_];

    rc[tid] = rep_cur[b * D_ + tid];
    __syncthreads();

    float s = b_att[tid];
    for (int i = 0; i < D_; i++)
        s = fmaf(rc[i], W_att[(size_t)i * D_ + tid], s);
    qv[tid] = s;
    __syncthreads();

    const int w = tid >> 5, lane = tid & 31;
    float p = 0.f;
#pragma unroll
    for (int r = 0; r < 8; r++) {
        int d = lane + 32 * r;
        p = fmaf(rep[((size_t)b * NB_ + w) * D_ + d], qv[d], p);
    }
#pragma unroll
    for (int off = 16; off > 0; off >>= 1)
        p += __shfl_xor_sync(0xffffffffu, p, off);
    if (lane == 0) sc[w] = p * (1.0f / 16.0f);
    __syncthreads();

    if (tid == 0) {
        float sv[NB_];
        float mx = -1e30f;
#pragma unroll
        for (int n = 0; n < NB_; n++) {
            float v = (mask_session[b * NB_ + n] > 0.f) ? sc[n] : -1e9f;
            sv[n] = v;
            mx = fmaxf(mx, v);
        }
        float den = 0.f;
#pragma unroll
        for (int n = 0; n < NB_; n++) {
            sv[n] = expf(sv[n] - mx);
            den += sv[n];
        }
        float inv = 1.0f / den;
        float acc = 0.f;
#pragma unroll
        for (int n = 0; n < NB_; n++)
            acc += g_score[b * NB_ + n] * sv[n] * inv;
        out[b] = acc;
    }
}

// ---------------------------------------------------------------------------
extern "C" void kernel_launch(void* const* d_in, const int* in_sizes, int n_in,
                              void* d_out, int out_size)
{
    const float* word_atten   = (const float*)d_in[0];
    const float* hq           = (const float*)d_in[1];
    const float* can          = (const float*)d_in[2];
    const float* rep          = (const float*)d_in[3];
    const float* rep_cur      = (const float*)d_in[4];
    const float* mask_hq      = (const float*)d_in[5];
    const float* mask_can     = (const float*)d_in[6];
    const float* mask_session = (const float*)d_in[7];
    const float* W_dense      = (const float*)d_in[8];
    const float* b_dense      = (const float*)d_in[9];
    const float* W_att        = (const float*)d_in[10];
    const float* b_att        = (const float*)d_in[11];
    float* out = (float*)d_out;

    // 32768 rows (16384 hq + 16384 can), 8 rows per block
    norms_kernel<<<4096, 256>>>(hq, can);

    dim3 grid2(NB_, B_);
    knrm_kernel<<<grid2, 128>>>(hq, can, word_atten, mask_hq, mask_can,
                                mask_session, W_dense, b_dense);

    attend_kernel<<<B_, 256>>>(rep, rep_cur, mask_session, W_att, b_att, out);
}

// round 15
// speedup vs baseline: 1.2846x; 1.2846x over previous
#include <cuda_runtime.h>
#include <math.h>

// ---------------------------------------------------------------------------
// AttentiveKnrmLayer  (B=64, NB=8, Q=32, T=256, D=256, N_BINS=11)
//
//  0 word_atten   [B,NB,Q]   f32      6 mask_can     [B,T]    f32
//  1 hq           [B,NB,Q,D] f32      7 mask_session [B,NB]   f32
//  2 can          [B,T,D]    f32      8 W_dense      [11,1]   f32
//  3 rep          [B,NB,D]   f32      9 b_dense      [1]      f32
//  4 rep_cur      [B,D]      f32     10 W_att        [D,D]    f32
//  5 mask_hq      [B,NB,Q]   f32     11 b_att        [D]      f32
//  output: [B] f32
//
// R15: scalar GEMM retiled 8q x 4t (smem crossbar 24 cyc < FMA 32 cyc per
// warp-step -> FMA-bound), normalization folded into epilogue, Gaussian
// ratio-chain (3 MUFU/elem instead of 11), MLP=4 norms kernel.
// ---------------------------------------------------------------------------

#define B_    64
#define NB_   8
#define Q_    32
#define T_    256
#define D_    256
#define NBIN  11

// scratch (no cudaMalloc allowed)
__device__ float g_inv_hq[B_ * NB_ * Q_];   // 1/max(||hq row||, eps)
__device__ float g_inv_can[B_ * T_];        // 1/max(||can row||, eps)
__device__ float g_score[B_ * NB_];         // tanh(pooled @ W_dense + b)

// ---------------------------------------------------------------------------
// Kernel 1: inverse L2 norms. Warp handles 2 rows; 16 lanes x 16 floats each
// (4 float4 per lane -> MLP=4). rows [0,16384) -> hq, rest -> can.
// ---------------------------------------------------------------------------
__global__ __launch_bounds__(256) void norms_kernel(
    const float* __restrict__ hq, const float* __restrict__ can)
{
    const int warp = threadIdx.x >> 5;
    const int lane = threadIdx.x & 31;
    const int row  = (blockIdx.x * 8 + warp) * 2 + (lane >> 4);
    const int sub  = lane & 15;               // 16 lanes per row

    const float* src;
    float* dst;
    if (row < B_ * NB_ * Q_) {
        src = hq + (size_t)row * D_;
        dst = g_inv_hq + row;
    } else {
        src = can + (size_t)(row - B_ * NB_ * Q_) * D_;
        dst = g_inv_can + (row - B_ * NB_ * Q_);
    }

    const float4* s4 = (const float4*)&src[sub * 16];
    float4 v0 = s4[0], v1 = s4[1], v2 = s4[2], v3 = s4[3];
    float ss = v0.x * v0.x + v0.y * v0.y + v0.z * v0.z + v0.w * v0.w;
    ss += v1.x * v1.x + v1.y * v1.y + v1.z * v1.z + v1.w * v1.w;
    ss += v2.x * v2.x + v2.y * v2.y + v2.z * v2.z + v2.w * v2.w;
    ss += v3.x * v3.x + v3.y * v3.y + v3.z * v3.z + v3.w * v3.w;

#pragma unroll
    for (int off = 8; off > 0; off >>= 1)       // reduce within 16-lane group
        ss += __shfl_xor_sync(0xffffffffu, ss, off);

    if (sub == 0)
        *dst = 1.0f / fmaxf(sqrtf(ss), 1e-10f);
}

// ---------------------------------------------------------------------------
// Kernel 2: per (b,n): fp32 GEMM (32x256 @ 256x256^T) fused with Gaussian
// soft-binning, log-pool over T, weighted sum over Q, dense + tanh.
//
// Grid (NB, B), block 256 = 8 warps.
// Warp w: q-group qg = w&3 (8 q's), t-half th = w>>2 (t = th*128 + j*32 + tt).
// Per 4-k step per warp: 4 LDS.128 (cv) + 8 broadcast LDS.128 (a) = 24 smem
// cycles vs 128 FFMA = 32 issue cycles -> FMA-pipe bound.
// ---------------------------------------------------------------------------
__global__ __launch_bounds__(256) void knrm_kernel(
    const float* __restrict__ hq_g,
    const float* __restrict__ can_g,
    const float* __restrict__ word_atten,
    const float* __restrict__ mask_hq,
    const float* __restrict__ mask_can,
    const float* __restrict__ mask_session,
    const float* __restrict__ W_dense,
    const float* __restrict__ b_dense)
{
    const int n  = blockIdx.x;
    const int b  = blockIdx.y;
    const int bn = b * NB_ + n;

    const float* hqp = hq_g + (size_t)bn * Q_ * D_;
    const float* cnp = can_g + (size_t)b * T_ * D_;

    __shared__ __align__(16) float cs[T_][36];     // 36 KB  (K-chunk of can)
    __shared__ __align__(16) float hq_s[Q_][36];   // 4.6 KB (K-chunk of hq)
    __shared__ float lpw[Q_][2][12];               // per (q, t-half) bins
    __shared__ float lp2[Q_][12];                  // log-pooled, weighted
    __shared__ float pooled_s[NBIN];

    const int tid = threadIdx.x;
    const int tt  = tid & 31;
    const int wid = tid >> 5;
    const int qg  = wid & 3;
    const int th  = wid >> 2;
    const int q0  = qg * 8;
    const int tb  = th * 128;

    float acc[8][4];
#pragma unroll
    for (int i = 0; i < 8; i++)
#pragma unroll
        for (int j = 0; j < 4; j++) acc[i][j] = 0.f;

    const int c  = tid & 7;    // float4 column within K-chunk
    const int r0 = tid >> 3;   // 0..31 staging row

    // ---- GEMM: K chunked by 32 --------------------------------------------
    for (int k0 = 0; k0 < D_; k0 += 32) {
        __syncthreads();   // previous chunk fully consumed

        // stage can chunk: 256 rows x 32 floats
#pragma unroll
        for (int p = 0; p < 8; p++) {
            int t = p * 32 + r0;
            float4 v = *(const float4*)&cnp[(size_t)t * D_ + k0 + c * 4];
            *(float4*)&cs[t][c * 4] = v;
        }
        // stage hq chunk: 32 rows x 32 floats
        {
            float4 h = *(const float4*)&hqp[(size_t)r0 * D_ + k0 + c * 4];
            *(float4*)&hq_s[r0][c * 4] = h;
        }
        __syncthreads();

#pragma unroll
        for (int kk = 0; kk < 32; kk += 4) {
            float4 cv[4];
#pragma unroll
            for (int j = 0; j < 4; j++)
                cv[j] = *(const float4*)&cs[tb + j * 32 + tt][kk];
#pragma unroll
            for (int i = 0; i < 8; i++) {
                float4 a = *(const float4*)&hq_s[q0 + i][kk];
#pragma unroll
                for (int j = 0; j < 4; j++)
                    acc[i][j] = fmaf(a.x, cv[j].x,
                                fmaf(a.y, cv[j].y,
                                fmaf(a.z, cv[j].z,
                                fmaf(a.w, cv[j].w, acc[i][j]))));
            }
        }
    }

    // ---- epilogue: normalize, Gaussian bins (ratio chain), pool over T -----
    float mc[4], it[4];
#pragma unroll
    for (int j = 0; j < 4; j++) {
        int t = tb + j * 32 + tt;
        mc[j] = mask_can[b * T_ + t];
        it[j] = g_inv_can[b * T_ + t];
    }

    // exact-match bin: exp2(d^2 * C2_0); soft bins: k1 = exp2(d1^2 * C2_S),
    // k_{j+1} = k_j * r,  r <- r * exp(-4),  r1 = exp(16 - 20 m).
    const float C2_0 = -721347.52f;       // -log2(e)/(2e-6)
    const float C2_S = -72.13475204f;     // -log2(e)/0.02
    const float RS   = 0.0183156389f;     // exp(-4)

#pragma unroll
    for (int i = 0; i < 8; i++) {
        const int q = q0 + i;
        const float invq = g_inv_hq[bn * Q_ + q];

        float bins[NBIN];
#pragma unroll
        for (int bb = 0; bb < NBIN; bb++) bins[bb] = 0.f;

#pragma unroll
        for (int j = 0; j < 4; j++) {
            float m = acc[i][j] * (invq * it[j]);
            float w = mc[j];
            float d0 = m - 1.0f;
            bins[0] = fmaf(exp2f(d0 * d0 * C2_0), w, bins[0]);
            float d1 = m - 0.9f;
            float k = exp2f(d1 * d1 * C2_S);
            // r1 = exp(16 - 20m) = exp2(23.08312067 - 28.85390082 m)
            float r = exp2f(fmaf(m, -28.85390082f, 23.08312067f));
            bins[1] = fmaf(k, w, bins[1]);
#pragma unroll
            for (int bb = 2; bb < NBIN; bb++) {
                k *= r;
                r *= RS;
                bins[bb] = fmaf(k, w, bins[bb]);
            }
        }
#pragma unroll
        for (int bb = 0; bb < NBIN; bb++) {
            float s = bins[bb];
#pragma unroll
            for (int off = 16; off > 0; off >>= 1)
                s += __shfl_xor_sync(0xffffffffu, s, off);
            bins[bb] = s;
        }
        if (tt == 0) {
#pragma unroll
            for (int bb = 0; bb < NBIN; bb++)
                lpw[q][th][bb] = bins[bb];
        }
    }
    __syncthreads();

    // ---- combine halves, clip+log, weight by mask_hq * word_atten ----------
    for (int idx = tid; idx < Q_ * NBIN; idx += 256) {
        int q  = idx / NBIN;
        int bb = idx - q * NBIN;
        float s = lpw[q][0][bb] + lpw[q][1][bb];
        float w = mask_hq[bn * Q_ + q] * word_atten[bn * Q_ + q];
        lp2[q][bb] = logf(fmaxf(s, 1e-10f)) * 0.01f * w;
    }
    __syncthreads();

    // ---- sum over Q (fixed order), mask_session ----------------------------
    if (tid < NBIN) {
        float s = 0.f;
#pragma unroll
        for (int q = 0; q < Q_; q++) s += lp2[q][tid];
        pooled_s[tid] = s * mask_session[bn];
    }
    __syncthreads();

    // ---- dense + tanh -------------------------------------------------------
    if (tid == 0) {
        float z = b_dense[0];
#pragma unroll
        for (int bb = 0; bb < NBIN; bb++) z += pooled_s[bb] * W_dense[bb];
        g_score[bn] = tanhf(z);
    }
}

// ---------------------------------------------------------------------------
// Kernel 3: session attention + final combine. One block per batch b.
// ---------------------------------------------------------------------------
__global__ __launch_bounds__(256) void attend_kernel(
    const float* __restrict__ rep,
    const float* __restrict__ rep_cur,
    const float* __restrict__ mask_session,
    const float* __restrict__ W_att,
    const float* __restrict__ b_att,
    float* __restrict__ out)
{
    const int b = blockIdx.x;
    const int tid = threadIdx.x;

    __shared__ float rc[D_];
    __shared__ float qv[D_];
    __shared__ float sc[NB_];

    rc[tid] = rep_cur[b * D_ + tid];
    __syncthreads();

    float s = b_att[tid];
    for (int i = 0; i < D_; i++)
        s = fmaf(rc[i], W_att[(size_t)i * D_ + tid], s);
    qv[tid] = s;
    __syncthreads();

    const int w = tid >> 5, lane = tid & 31;
    float p = 0.f;
#pragma unroll
    for (int r = 0; r < 8; r++) {
        int d = lane + 32 * r;
        p = fmaf(rep[((size_t)b * NB_ + w) * D_ + d], qv[d], p);
    }
#pragma unroll
    for (int off = 16; off > 0; off >>= 1)
        p += __shfl_xor_sync(0xffffffffu, p, off);
    if (lane == 0) sc[w] = p * (1.0f / 16.0f);
    __syncthreads();

    if (tid == 0) {
        float sv[NB_];
        float mx = -1e30f;
#pragma unroll
        for (int n = 0; n < NB_; n++) {
            float v = (mask_session[b * NB_ + n] > 0.f) ? sc[n] : -1e9f;
            sv[n] = v;
            mx = fmaxf(mx, v);
        }
        float den = 0.f;
#pragma unroll
        for (int n = 0; n < NB_; n++) {
            sv[n] = expf(sv[n] - mx);
            den += sv[n];
        }
        float inv = 1.0f / den;
        float acc = 0.f;
#pragma unroll
        for (int n = 0; n < NB_; n++)
            acc += g_score[b * NB_ + n] * sv[n] * inv;
        out[b] = acc;
    }
}

// ---------------------------------------------------------------------------
extern "C" void kernel_launch(void* const* d_in, const int* in_sizes, int n_in,
                              void* d_out, int out_size)
{
    const float* word_atten   = (const float*)d_in[0];
    const float* hq           = (const float*)d_in[1];
    const float* can          = (const float*)d_in[2];
    const float* rep          = (const float*)d_in[3];
    const float* rep_cur      = (const float*)d_in[4];
    const float* mask_hq      = (const float*)d_in[5];
    const float* mask_can     = (const float*)d_in[6];
    const float* mask_session = (const float*)d_in[7];
    const float* W_dense      = (const float*)d_in[8];
    const float* b_dense      = (const float*)d_in[9];
    const float* W_att        = (const float*)d_in[10];
    const float* b_att        = (const float*)d_in[11];
    float* out = (float*)d_out;

    // 32768 rows, 16 rows per block
    norms_kernel<<<2048, 256>>>(hq, can);

    dim3 grid2(NB_, B_);
    knrm_kernel<<<grid2, 256>>>(hq, can, word_atten, mask_hq, mask_can,
                                mask_session, W_dense, b_dense);

    attend_kernel<<<B_, 256>>>(rep, rep_cur, mask_session, W_att, b_att, out);
}